// round 17
// baseline (speedup 1.0000x reference)
#include <cuda_runtime.h>
#include <cuda_fp16.h>
#include <math.h>
#include <stdint.h>

#define KDIM   768
#define HEADS  8
#define KH     6144
#define QKVN   18432   // 3 * KH
#define TSEQ   1024
#define NBATCH 2
#define BT     2048
#define VOCAB  32000
#define FFD    3072

// ---------------- scratch (device globals; no runtime allocation) ----------
__device__ __half  h_xe [BT * KDIM];
__device__ __half  h_qkv[(size_t)BT * QKVN];                     // q|k|v fused
__device__ __half  h_p  [(size_t)NBATCH * HEADS * TSEQ * TSEQ];  // scores/probs
__device__ __half  h_y  [BT * KH];
__device__ float   g_t1 [2 * BT * KDIM];                         // split-K partials
__device__ __half  h_t2 [BT * KDIM];
__device__ __half  h_ff [BT * FFD];
// fp16 fragment-major weights
__device__ __half hw_qkv[(size_t)2 * KDIM * QKVN];
__device__ __half hw_u  [2 * KH * KDIM];
__device__ __half hw_f1 [2 * KDIM * FFD];
__device__ __half hw_f2 [2 * FFD * KDIM];
__device__ __half hw_o  [KDIM * VOCAB];

// ---------------- helpers ----------------------------------------------------
__device__ __forceinline__ uint32_t smem_u32(const void* p) {
    uint32_t a;
    asm("{ .reg .u64 t; cvta.to.shared.u64 t, %1; cvt.u32.u64 %0, t; }" : "=r"(a) : "l"(p));
    return a;
}
__device__ __forceinline__ void cp16(uint32_t saddr, const void* g) {
    asm volatile("cp.async.cg.shared.global [%0], [%1], 16;"
                 :: "r"(saddr), "l"(g) : "memory");
}
__device__ __forceinline__ void cp_commit() {
    asm volatile("cp.async.commit_group;" ::: "memory");
}
__device__ __forceinline__ void cp_wait2() {
    asm volatile("cp.async.wait_group 2;" ::: "memory");
}
__device__ __forceinline__ void mma16816(float c[4], uint32_t a0, uint32_t a1,
                                         uint32_t a2, uint32_t a3,
                                         uint32_t b0, uint32_t b1) {
    asm volatile(
        "mma.sync.aligned.m16n8k16.row.col.f32.f16.f16.f32 "
        "{%0,%1,%2,%3}, {%4,%5,%6,%7}, {%8,%9}, {%0,%1,%2,%3};"
        : "+f"(c[0]), "+f"(c[1]), "+f"(c[2]), "+f"(c[3])
        : "r"(a0), "r"(a1), "r"(a2), "r"(a3), "r"(b0), "r"(b1));
}
__device__ __forceinline__ uint32_t packh2(float lo, float hi) {
    __half2 h = __floats2half2_rn(lo, hi);
    return *(uint32_t*)&h;
}

// ---------------- fp16 GEMM: 256 thr, 64 x BN block, BK=16, 4-stage ---------
// 8 warps (2M x 4N), warp 32 x BN/4, 2 CTAs/SM. Proven R13/R15 configuration.
// BMODE 0: gmem [N,K]; BMODE 1: gmem [K,N] padded; BMODE 2: FRAG weights.
// EPI: 0 none, 1 *scale, 2 +bias, 3 +bias + exact GELU. OUTH: fp16 out.
template <int EPI, int BMODE, int BN, bool OUTH>
__global__ void __launch_bounds__(256, 2) gemm_h(
    const __half* __restrict__ A, const __half* __restrict__ B,
    void* __restrict__ Cv, const float* __restrict__ bias,
    int Kd, int lda, int ldb, int ldc,
    long long zAb, long long zAh, long long zBb, long long zBh,
    long long zCb, long long zCh, int Hn, float scale)
{
    constexpr int NT_ = BN / 32;
    constexpr int RS1 = BN * 2 + 16;
    constexpr int BSTB = (BMODE == 1) ? 16 * RS1 : BN * 32;
    constexpr int STGB = 2048 + BSTB;
    extern __shared__ char smc[];
    const uint32_t sbase = smem_u32(smc);

    const int tid = threadIdx.x;
    const int lane = tid & 31, wid = tid >> 5;
    const int g = lane >> 2, tig = lane & 3;
    const int bx = blockIdx.x, by = blockIdx.y, bz = blockIdx.z;
    float* Cf = (float*)Cv;
    __half* Ch = (__half*)Cv;
    {
        const int zb = bz / Hn, zh = bz % Hn;
        A += (size_t)zb * zAb + (size_t)zh * zAh;
        B += (size_t)zb * zBb + (size_t)zh * zBh;
        Cf += (size_t)zb * zCb + (size_t)zh * zCh;
        Ch += (size_t)zb * zCb + (size_t)zh * zCh;
    }

    const int mA = tid >> 1, cA = tid & 1;
    const __half* Ag = A + (size_t)(by * 64 + mA) * lda + cA * 8;
    const uint32_t awb = (uint32_t)(mA * 32 + ((cA * 16) ^ ((mA & 4) << 2)));

    const __half* Bg = (BMODE == 0) ? (B + (size_t)bx * BN * ldb)
                     : (BMODE == 1) ? (B + (size_t)bx * BN)
                                    : (B + (size_t)bx * BN * 16);

    float acc[2][NT_][4];
#pragma unroll
    for (int i = 0; i < 2; i++)
#pragma unroll
        for (int j = 0; j < NT_; j++)
#pragma unroll
            for (int c = 0; c < 4; c++) acc[i][j][c] = 0.f;

    const int NTILES = Kd >> 4;

    auto issue = [&](int kt) {
        const uint32_t sa = sbase + (uint32_t)(kt & 3) * STGB;
        if (tid < 128) cp16(sa + awb, Ag + kt * 16);
        const uint32_t sb = sa + 2048;
#pragma unroll
        for (int j = 0; j < BN / 128; j++) {
            const int ch = tid + 256 * j;
            if (BMODE == 0) {
                const int n = ch >> 1, c = ch & 1;
                cp16(sb + n * 32 + ((c * 16) ^ ((n & 4) << 2)),
                     Bg + (size_t)n * ldb + kt * 16 + c * 8);
            } else if (BMODE == 1) {
                const int k = ch / (BN / 8), c = ch % (BN / 8);
                cp16(sb + k * RS1 + c * 16,
                     Bg + (size_t)(kt * 16 + k) * ldb + c * 8);
            } else {
                cp16(sb + ch * 16, Bg + (size_t)kt * 16 * ldb + ch * 8);
            }
        }
    };

#pragma unroll
    for (int s = 0; s < 3; s++) { issue(s); cp_commit(); }

    const int wm = (wid & 1) * 32, wn = (wid >> 1) * (BN / 4);
    const int nbase = (wid >> 1) * NT_;

    for (int kt = 0; kt < NTILES; kt++) {
        cp_wait2();
        __syncthreads();

        const char* As = smc + (kt & 3) * STGB;
        const char* Bs = As + 2048;

        uint32_t af[2][4];
#pragma unroll
        for (int mt = 0; mt < 2; mt++) {
            const int m0 = wm + mt * 16 + g;
            const int sw = (m0 & 4) << 2;
            af[mt][0] = *(const uint32_t*)(As + m0 * 32 + ((tig * 4) ^ sw));
            af[mt][1] = *(const uint32_t*)(As + (m0 + 8) * 32 + ((tig * 4) ^ sw));
            af[mt][2] = *(const uint32_t*)(As + m0 * 32 + ((tig * 4 + 16) ^ sw));
            af[mt][3] = *(const uint32_t*)(As + (m0 + 8) * 32 + ((tig * 4 + 16) ^ sw));
        }

#pragma unroll
        for (int nt = 0; nt < NT_; nt++) {
            uint32_t b0, b1;
            if (BMODE == 2) {
                uint2 bv = *(const uint2*)(Bs + (nbase + nt) * 256 + lane * 8);
                b0 = bv.x; b1 = bv.y;
            } else if (BMODE == 0) {
                const int n0 = wn + nt * 8 + g;
                const int sw = (n0 & 4) << 2;
                b0 = *(const uint32_t*)(Bs + n0 * 32 + ((tig * 4) ^ sw));
                b1 = *(const uint32_t*)(Bs + n0 * 32 + ((tig * 4 + 16) ^ sw));
            } else {
                const int n0 = wn + nt * 8 + g;
                const __half* p00 = (const __half*)(Bs + (2 * tig) * RS1 + n0 * 2);
                const __half* p01 = (const __half*)(Bs + (2 * tig + 1) * RS1 + n0 * 2);
                const __half* p10 = (const __half*)(Bs + (2 * tig + 8) * RS1 + n0 * 2);
                const __half* p11 = (const __half*)(Bs + (2 * tig + 9) * RS1 + n0 * 2);
                __half2 v0 = __halves2half2(*p00, *p01);
                __half2 v1 = __halves2half2(*p10, *p11);
                b0 = *(uint32_t*)&v0; b1 = *(uint32_t*)&v1;
            }
#pragma unroll
            for (int mt = 0; mt < 2; mt++)
                mma16816(acc[mt][nt], af[mt][0], af[mt][1], af[mt][2], af[mt][3],
                         b0, b1);
        }

        if (kt + 3 < NTILES) issue(kt + 3);
        cp_commit();
    }

    // ---- epilogue ----
#pragma unroll
    for (int mt = 0; mt < 2; mt++) {
        const int r0 = by * 64 + wm + mt * 16 + g;
#pragma unroll
        for (int nt = 0; nt < NT_; nt++) {
            const int col = bx * BN + wn + nt * 8 + 2 * tig;
            float c0 = acc[mt][nt][0], c1 = acc[mt][nt][1];
            float c2 = acc[mt][nt][2], c3 = acc[mt][nt][3];
            if (EPI == 1) {
                c0 *= scale; c1 *= scale; c2 *= scale; c3 *= scale;
            } else if (EPI >= 2) {
                const float b0 = bias[col], b1 = bias[col + 1];
                c0 += b0; c1 += b1; c2 += b0; c3 += b1;
                if (EPI == 3) {
                    c0 = 0.5f * c0 * (1.0f + erff(c0 * 0.7071067811865476f));
                    c1 = 0.5f * c1 * (1.0f + erff(c1 * 0.7071067811865476f));
                    c2 = 0.5f * c2 * (1.0f + erff(c2 * 0.7071067811865476f));
                    c3 = 0.5f * c3 * (1.0f + erff(c3 * 0.7071067811865476f));
                }
            }
            if (OUTH) {
                *(uint32_t*)(Ch + (size_t)r0 * ldc + col) = packh2(c0, c1);
                *(uint32_t*)(Ch + (size_t)(r0 + 8) * ldc + col) = packh2(c2, c3);
            } else {
                *(float2*)(Cf + (size_t)r0 * ldc + col) = make_float2(c0, c1);
                *(float2*)(Cf + (size_t)(r0 + 8) * ldc + col) = make_float2(c2, c3);
            }
        }
    }
}

// ---------------- weight -> fp16 fragment-major transform (smem-tiled) ------
// Block = 256 threads, tile = 16 k x 256 n.
// Loads: coalesced float4 rows. Writes: each thread 16 contiguous halves (32B).
// Output for tile (kb, n0) occupies halves [kb*16*Ndst + (n0+noff)*16, +4096).
__global__ void __launch_bounds__(256) wcvt2(const float* __restrict__ s,
                                             __half* __restrict__ d,
                                             int Nsrc, int Ndst, int noff)
{
    __shared__ float sm[16][260];
    const int kb = blockIdx.y;
    const int n0 = blockIdx.x * 256;
    const int t = threadIdx.x;

    // load 16 x 256 floats, coalesced
    const int r = t >> 4, c0 = (t & 15) * 16;
    const float* src = s + (size_t)(kb * 16 + r) * Nsrc + n0 + c0;
#pragma unroll
    for (int i = 0; i < 4; i++) {
        float4 v = *(const float4*)(src + i * 4);
        sm[r][c0 + i * 4 + 0] = v.x;
        sm[r][c0 + i * 4 + 1] = v.y;
        sm[r][c0 + i * 4 + 2] = v.z;
        sm[r][c0 + i * 4 + 3] = v.w;
    }
    __syncthreads();

    // write 16 contiguous halves per thread in fragment order
    __half* dst = d + (size_t)kb * 16 * Ndst + (size_t)(n0 + noff) * 16 + t * 16;
    uint32_t w[8];
#pragma unroll
    for (int j = 0; j < 8; j++) {
        const int p0 = t * 16 + 2 * j;
        float f[2];
#pragma unroll
        for (int e = 0; e < 2; e++) {
            const int p = p0 + e;
            const int nb = p >> 7, lane = (p >> 2) & 31, cc = p & 3;
            const int n_loc = nb * 8 + (lane >> 2);
            const int k_loc = 2 * (lane & 3) + (cc & 1) + ((cc >> 1) << 3);
            f[e] = sm[k_loc][n_loc];
        }
        w[j] = packh2(f[0], f[1]);
    }
    uint4 o0 = make_uint4(w[0], w[1], w[2], w[3]);
    uint4 o1 = make_uint4(w[4], w[5], w[6], w[7]);
    *(uint4*)(dst + 0) = o0;
    *(uint4*)(dst + 8) = o1;
}

// ---------------- embedding + positional encoding (fp16 out) ---------------
__global__ void embed_k(const int* __restrict__ x, const float* __restrict__ emb,
                        __half* __restrict__ xe)
{
    const int row = blockIdx.x;
    const int t = row & (TSEQ - 1);
    const int tok = x[row];
    const float* e = emb + (size_t)tok * KDIM;
    for (int c = threadIdx.x; c < KDIM; c += blockDim.x) {
        const int j = c >> 1;
        const float expo = (2.0f * (float)(2 * j)) / (float)KDIM;
        const float div = powf(10000.0f, expo);
        const float ang = (float)t / div;
        const float pe = (c & 1) ? cosf(ang) : sinf(ang);
        xe[(size_t)row * KDIM + c] = __float2half(e[c] + pe);
    }
}

// ---------------- row softmax: fp16 in-place --------------------------------
__global__ void __launch_bounds__(256) softmax_k(__half* __restrict__ s)
{
    __half* p = s + (size_t)blockIdx.x * TSEQ;
    const int tid = threadIdx.x;
    __shared__ float sh[8];

    float v[4];
    float m = -3.4e38f;
#pragma unroll
    for (int i = 0; i < 4; i++) { v[i] = __half2float(p[tid + i * 256]); m = fmaxf(m, v[i]); }
#pragma unroll
    for (int off = 16; off > 0; off >>= 1) m = fmaxf(m, __shfl_xor_sync(0xffffffffu, m, off));
    if ((tid & 31) == 0) sh[tid >> 5] = m;
    __syncthreads();
    m = fmaxf(fmaxf(fmaxf(sh[0], sh[1]), fmaxf(sh[2], sh[3])),
              fmaxf(fmaxf(sh[4], sh[5]), fmaxf(sh[6], sh[7])));
    __syncthreads();

    float sum = 0.f;
#pragma unroll
    for (int i = 0; i < 4; i++) { v[i] = expf(v[i] - m); sum += v[i]; }
#pragma unroll
    for (int off = 16; off > 0; off >>= 1) sum += __shfl_xor_sync(0xffffffffu, sum, off);
    if ((tid & 31) == 0) sh[tid >> 5] = sum;
    __syncthreads();
    sum = sh[0] + sh[1] + sh[2] + sh[3] + sh[4] + sh[5] + sh[6] + sh[7];
    const float inv = 1.0f / sum;
#pragma unroll
    for (int i = 0; i < 4; i++) p[tid + i * 256] = __float2half(v[i] * inv);
}

// ---------------- layernorm over (a + b + bias): fp32x2 in, fp16 out --------
__global__ void __launch_bounds__(256) lnsum_k(const float* __restrict__ ina,
                                               const float* __restrict__ inb,
                                               const float* __restrict__ bias,
                                               __half* __restrict__ out,
                                               const float* __restrict__ gw,
                                               const float* __restrict__ bw)
{
    const float* pa = ina + (size_t)blockIdx.x * KDIM;
    const float* pb = inb + (size_t)blockIdx.x * KDIM;
    __half* o = out + (size_t)blockIdx.x * KDIM;
    const int tid = threadIdx.x;
    __shared__ float sh[8];

    float v[3];
    float s = 0.f;
#pragma unroll
    for (int i = 0; i < 3; i++) {
        const int c = tid + i * 256;
        v[i] = pa[c] + pb[c] + bias[c];
        s += v[i];
    }
#pragma unroll
    for (int off = 16; off > 0; off >>= 1) s += __shfl_xor_sync(0xffffffffu, s, off);
    if ((tid & 31) == 0) sh[tid >> 5] = s;
    __syncthreads();
    const float mu = (sh[0] + sh[1] + sh[2] + sh[3] + sh[4] + sh[5] + sh[6] + sh[7])
                     * (1.0f / (float)KDIM);
    __syncthreads();

    float vs = 0.f;
#pragma unroll
    for (int i = 0; i < 3; i++) { const float d = v[i] - mu; vs += d * d; }
#pragma unroll
    for (int off = 16; off > 0; off >>= 1) vs += __shfl_xor_sync(0xffffffffu, vs, off);
    if ((tid & 31) == 0) sh[tid >> 5] = vs;
    __syncthreads();
    const float var = (sh[0] + sh[1] + sh[2] + sh[3] + sh[4] + sh[5] + sh[6] + sh[7])
                      * (1.0f / (float)KDIM);
    const float inv = rsqrtf(var + 1e-5f);
#pragma unroll
    for (int i = 0; i < 3; i++) {
        const int c = tid + i * 256;
        o[c] = __float2half((v[i] - mu) * inv * gw[c] + bw[c]);
    }
}

// ---------------- final layernorm: fp16 in, fp16 out -------------------------
__global__ void __launch_bounds__(256) lnf_k(const __half* __restrict__ in,
                                             __half* __restrict__ out,
                                             const float* __restrict__ gw,
                                             const float* __restrict__ bw)
{
    const __half* pin = in + (size_t)blockIdx.x * KDIM;
    __half* o = out + (size_t)blockIdx.x * KDIM;
    const int tid = threadIdx.x;
    __shared__ float sh[8];

    float v[3];
    float s = 0.f;
#pragma unroll
    for (int i = 0; i < 3; i++) { v[i] = __half2float(pin[tid + i * 256]); s += v[i]; }
#pragma unroll
    for (int off = 16; off > 0; off >>= 1) s += __shfl_xor_sync(0xffffffffu, s, off);
    if ((tid & 31) == 0) sh[tid >> 5] = s;
    __syncthreads();
    const float mu = (sh[0] + sh[1] + sh[2] + sh[3] + sh[4] + sh[5] + sh[6] + sh[7])
                     * (1.0f / (float)KDIM);
    __syncthreads();

    float vs = 0.f;
#pragma unroll
    for (int i = 0; i < 3; i++) { const float d = v[i] - mu; vs += d * d; }
#pragma unroll
    for (int off = 16; off > 0; off >>= 1) vs += __shfl_xor_sync(0xffffffffu, vs, off);
    if ((tid & 31) == 0) sh[tid >> 5] = vs;
    __syncthreads();
    const float var = (sh[0] + sh[1] + sh[2] + sh[3] + sh[4] + sh[5] + sh[6] + sh[7])
                      * (1.0f / (float)KDIM);
    const float inv = rsqrtf(var + 1e-5f);
#pragma unroll
    for (int i = 0; i < 3; i++) {
        const int c = tid + i * 256;
        o[c] = __float2half((v[i] - mu) * inv * gw[c] + bw[c]);
    }
}

// ---------------- host dispatch ----------------------------------------------
template <int EPI, int BM, int BN, bool OUTH>
static inline void launch_gemm(const __half* A, const __half* B, void* C,
                               const float* bias,
                               int M, int N, int Kd, int lda, int ldb, int ldc,
                               long long zAb, long long zAh, long long zBb,
                               long long zBh, long long zCb, long long zCh,
                               int Z, int Hn, float scale)
{
    constexpr int RS1 = BN * 2 + 16;
    constexpr int BSTB = (BM == 1) ? 16 * RS1 : BN * 32;
    constexpr int SMEMB = 4 * (2048 + BSTB);
    cudaFuncSetAttribute(gemm_h<EPI, BM, BN, OUTH>,
                         cudaFuncAttributeMaxDynamicSharedMemorySize, SMEMB);
    dim3 gr(N / BN, M / 64, Z);
    gemm_h<EPI, BM, BN, OUTH><<<gr, 256, SMEMB>>>(A, B, C, bias, Kd, lda, ldb, ldc,
                                                  zAb, zAh, zBb, zBh, zCb, zCh,
                                                  Hn, scale);
}

static inline void wcvt(const float* s, __half* d, int K, int Nsrc,
                        int Ndst, int noff)
{
    dim3 gr(Nsrc / 256, K / 16);
    wcvt2<<<gr, 256>>>(s, d, Nsrc, Ndst, noff);
}

extern "C" void kernel_launch(void* const* d_in, const int* in_sizes, int n_in,
                              void* d_out, int out_size)
{
    const int*   x    = (const int*)  d_in[0];
    const float* emb  = (const float*)d_in[1];
    const float* Wq   = (const float*)d_in[2];
    const float* Wk   = (const float*)d_in[3];
    const float* Wv   = (const float*)d_in[4];
    const float* Wu   = (const float*)d_in[5];
    const float* bu   = (const float*)d_in[6];
    const float* ln1g = (const float*)d_in[7];
    const float* ln1b = (const float*)d_in[8];
    const float* Wf1  = (const float*)d_in[9];
    const float* bf1  = (const float*)d_in[10];
    const float* Wf2  = (const float*)d_in[11];
    const float* bf2  = (const float*)d_in[12];
    const float* ln2g = (const float*)d_in[13];
    const float* ln2b = (const float*)d_in[14];
    const float* lnfg = (const float*)d_in[15];
    const float* lnfb = (const float*)d_in[16];
    const float* Wout = (const float*)d_in[17];
    const float* bout = (const float*)d_in[18];
    float* out = (float*)d_out;

    __half *xe, *qkv, *p, *y, *t2, *ff;
    float *t1;
    __half *wqkv_, *wu_, *wf1_, *wf2_, *wo_;
    cudaGetSymbolAddress((void**)&xe,  h_xe);
    cudaGetSymbolAddress((void**)&qkv, h_qkv);
    cudaGetSymbolAddress((void**)&p,   h_p);
    cudaGetSymbolAddress((void**)&y,   h_y);
    cudaGetSymbolAddress((void**)&t1,  g_t1);
    cudaGetSymbolAddress((void**)&t2,  h_t2);
    cudaGetSymbolAddress((void**)&ff,  h_ff);
    cudaGetSymbolAddress((void**)&wqkv_, hw_qkv);
    cudaGetSymbolAddress((void**)&wu_,   hw_u);
    cudaGetSymbolAddress((void**)&wf1_,  hw_f1);
    cudaGetSymbolAddress((void**)&wf2_,  hw_f2);
    cudaGetSymbolAddress((void**)&wo_,   hw_o);

    const float scale = 1.0f / sqrtf((float)KDIM);
    float* t1b = t1 + (size_t)BT * KDIM;

    wcvt(Wq,   wqkv_, 2 * KDIM, KH,   QKVN, 0);
    wcvt(Wk,   wqkv_, 2 * KDIM, KH,   QKVN, KH);
    wcvt(Wv,   wqkv_, 2 * KDIM, KH,   QKVN, 2 * KH);
    wcvt(Wu,   wu_,   2 * KH,   KDIM, KDIM, 0);
    wcvt(Wf1,  wf1_,  2 * KDIM, FFD,  FFD,  0);
    wcvt(Wf2,  wf2_,  2 * FFD,  KDIM, KDIM, 0);
    wcvt(Wout, wo_,   KDIM,     VOCAB, VOCAB, 0);

    embed_k<<<BT, 256>>>(x, emb, xe);

    for (int l = 0; l < 2; l++) {
        const __half* lwqkv = wqkv_ + (size_t)l * KDIM * QKVN;
        const __half* lwu   = wu_   + (size_t)l * KH * KDIM;
        const __half* qh = qkv;
        const __half* kh = qkv + KH;
        const __half* vh = qkv + 2 * KH;

        // fused QKV: [2048,768] x [768,18432] (FRAG), fp16 out
        launch_gemm<0, 2, 256, true>(xe, lwqkv, qkv, nullptr, BT, QKVN, KDIM,
                                     KDIM, QKVN, QKVN,
                                     0, 0, 0, 0, 0, 0, 1, 1, 0.f);

        // scores = Q K^T * scale  (BMODE 0, fp16 out)
        launch_gemm<1, 0, 256, true>(qh, kh, p, nullptr, TSEQ, TSEQ, KDIM,
                                     QKVN, QKVN, TSEQ,
                                     (long long)TSEQ * QKVN, KDIM,
                                     (long long)TSEQ * QKVN, KDIM,
                                     (long long)HEADS * TSEQ * TSEQ,
                                     (long long)TSEQ * TSEQ,
                                     NBATCH * HEADS, HEADS, scale);

        softmax_k<<<NBATCH * HEADS * TSEQ, 256>>>(p);

        // y = P @ V  (BMODE 1, BN=256, fp16 out)
        launch_gemm<0, 1, 256, true>(p, vh, y, nullptr, TSEQ, KDIM, TSEQ,
                                     TSEQ, QKVN, KH,
                                     (long long)HEADS * TSEQ * TSEQ,
                                     (long long)TSEQ * TSEQ,
                                     (long long)TSEQ * QKVN, KDIM,
                                     (long long)TSEQ * KH, KDIM,
                                     NBATCH * HEADS, HEADS, 0.f);

        // att partials: split-K=2 over KH (FRAG); bias folded into lnsum
        launch_gemm<0, 2, 128, false>(y, lwu, t1, nullptr, BT, KDIM, KH / 2,
                                      KH, KDIM, KDIM,
                                      0, KH / 2,
                                      0, (long long)(KH / 2) * KDIM,
                                      0, (long long)BT * KDIM,
                                      2, 2, 0.f);
        lnsum_k<<<BT, 256>>>(t1, t1b, bu + l * KDIM, t2,
                             ln1g + l * KDIM, ln1b + l * KDIM);

        // FFN1 (FRAG, GELU, fp16 out)
        launch_gemm<3, 2, 256, true>(t2, wf1_ + (size_t)l * KDIM * FFD, ff,
                                     bf1 + l * FFD, BT, FFD, KDIM,
                                     KDIM, FFD, FFD, 0, 0, 0, 0, 0, 0, 1, 1, 0.f);
        // FFN2 partials: split-K=2 over FFD (FRAG)
        launch_gemm<0, 2, 128, false>(ff, wf2_ + (size_t)l * FFD * KDIM, t1,
                                      nullptr, BT, KDIM, FFD / 2,
                                      FFD, KDIM, KDIM,
                                      0, FFD / 2,
                                      0, (long long)(FFD / 2) * KDIM,
                                      0, (long long)BT * KDIM,
                                      2, 2, 0.f);
        lnsum_k<<<BT, 256>>>(t1, t1b, bf2 + l * KDIM, xe,
                             ln2g + l * KDIM, ln2b + l * KDIM);
    }

    // final LN on fp16 xe -> fp16 t2
    lnf_k<<<BT, 256>>>(xe, t2, lnfg, lnfb);

    // logits = xf @ Wout + bout (FRAG, fp32 out)
    launch_gemm<2, 2, 256, false>(t2, wo_, out, bout, BT, VOCAB, KDIM,
                                  KDIM, VOCAB, VOCAB, 0, 0, 0, 0, 0, 0, 1, 1, 0.f);
}